// round 1
// baseline (speedup 1.0000x reference)
#include <cuda_runtime.h>
#include <cstdint>
#include <cstddef>

#define B_   32
#define T_   512
#define KIN  1024
#define H_   1024
#define G_   4096          // 4*H
#define M_   (B_*T_)       // 16384

// Scratch (device globals: allocation-free per harness rules)
__device__ float g_xproj[(size_t)M_ * G_];   // 256 MB: x@W_ih^T + b_ih
__device__ float g_h[2][B_*H_];              // double-buffered hidden state
__device__ float g_c[B_*H_];                 // cell state, [j][b]-major

typedef unsigned long long u64;

// sm_103a packed fp32 FMA (2 MACs/issue; ptxas won't auto-fuse — PTX only)
__device__ __forceinline__ void fma2(u64 &d, u64 a, u64 b){
    asm("fma.rn.f32x2 %0, %1, %2, %0;" : "+l"(d) : "l"(a), "l"(b));
}
__device__ __forceinline__ u64 pack2(float lo, float hi){
    u64 r; asm("mov.b64 %0, {%1,%2};" : "=l"(r) : "f"(lo), "f"(hi)); return r;
}
__device__ __forceinline__ float2 unpack2(u64 v){
    float2 f; asm("mov.b64 {%0,%1}, %2;" : "=f"(f.x), "=f"(f.y) : "l"(v)); return f;
}

// ------------------------------------------------------------------
// Phase 1: g_xproj[m][n] = sum_k inputs[m][k]*W_ih[n][k] + b_ih[n]
// 64x64 tile, BK=16, 256 threads, 4x4 per thread, f32x2 over n-pairs.
// A is staged duplicated as (a,a) pairs so inner loop has no packing.
// ------------------------------------------------------------------
#define P1_BM 64
#define P1_BN 64
#define P1_BK 16

__global__ void __launch_bounds__(256, 2) xproj_kernel(
    const float* __restrict__ A,      // inputs  [M_][KIN]
    const float* __restrict__ W,      // W_ih    [G_][KIN]
    const float* __restrict__ bias)   // b_ih    [G_]
{
    __shared__ __align__(16) u64   As2[P1_BK][P1_BM + 1];  // (a,a) pairs
    __shared__ __align__(16) float Bst[P1_BK][P1_BN + 2];  // [k][n]

    const int tid = threadIdx.x;
    const int m0 = blockIdx.y * P1_BM;
    const int n0 = blockIdx.x * P1_BN;
    const int tx = tid & 15;          // n tile (4 cols = 2 pairs)
    const int ty = tid >> 4;          // m tile (4 rows)

    const int lrow = tid >> 2;        // loader: 0..63
    const int lk   = (tid & 3) * 4;   // loader: 0,4,8,12

    u64 acc[4][2];
    #pragma unroll
    for (int i = 0; i < 4; i++) { acc[i][0] = 0ULL; acc[i][1] = 0ULL; }

    const float* Arow = A + (size_t)(m0 + lrow) * KIN + lk;
    const float* Wrow = W + (size_t)(n0 + lrow) * KIN + lk;

    for (int kc = 0; kc < KIN; kc += P1_BK) {
        float4 av = *(const float4*)(Arow + kc);
        float4 wv = *(const float4*)(Wrow + kc);
        As2[lk+0][lrow] = pack2(av.x, av.x);
        As2[lk+1][lrow] = pack2(av.y, av.y);
        As2[lk+2][lrow] = pack2(av.z, av.z);
        As2[lk+3][lrow] = pack2(av.w, av.w);
        Bst[lk+0][lrow] = wv.x;
        Bst[lk+1][lrow] = wv.y;
        Bst[lk+2][lrow] = wv.z;
        Bst[lk+3][lrow] = wv.w;
        __syncthreads();

        #pragma unroll
        for (int k = 0; k < P1_BK; k++) {
            u64 a0 = As2[k][ty*4+0];
            u64 a1 = As2[k][ty*4+1];
            u64 a2 = As2[k][ty*4+2];
            u64 a3 = As2[k][ty*4+3];
            u64 b0 = *(const u64*)&Bst[k][tx*4];
            u64 b1 = *(const u64*)&Bst[k][tx*4+2];
            fma2(acc[0][0], a0, b0); fma2(acc[0][1], a0, b1);
            fma2(acc[1][0], a1, b0); fma2(acc[1][1], a1, b1);
            fma2(acc[2][0], a2, b0); fma2(acc[2][1], a2, b1);
            fma2(acc[3][0], a3, b0); fma2(acc[3][1], a3, b1);
        }
        __syncthreads();
    }

    #pragma unroll
    for (int i = 0; i < 4; i++) {
        int m = m0 + ty*4 + i;
        float* crow = g_xproj + (size_t)m * G_ + n0 + tx*4;
        #pragma unroll
        for (int j = 0; j < 2; j++) {
            float2 v = unpack2(acc[i][j]);
            int n = n0 + tx*4 + 2*j;
            crow[2*j]   = v.x + bias[n];
            crow[2*j+1] = v.y + bias[n+1];
        }
    }
}

// ------------------------------------------------------------------
// Phase 2: one LSTM timestep.
// Block jb owns gate-units j in [jb*8, jb*8+8) => 32 preact columns
// (4 gates x 8 j) for all 32 batches. Grid = 128 blocks (one wave).
// 256 threads = 2 k-groups x 128; per thread 4b x 2c outputs,
// f32x2 over k-pairs. W tile is bank-rotation swizzled.
// ------------------------------------------------------------------
#define JT    8
#define NC    32
#define CHUNK 128
#define HSP   132   // hs row pitch (floats), 16B-aligned rows

__global__ void __launch_bounds__(256, 1) lstm_step_kernel(
    const float* __restrict__ Whh,    // [G_][KIN]
    const float* __restrict__ bhh,    // [G_]
    float* __restrict__ out,          // [logits | h_f | c_f]
    int t)
{
    __shared__ __align__(16) float hs[32][HSP];  // h chunk [b][k]
    __shared__ __align__(16) u64   ws[NC][64];   // W chunk, k-pairs, swizzled
    __shared__ float sp[NC][33];                 // preact staging [c][b]

    const int tid = threadIdx.x;
    const int jb  = blockIdx.x;                  // 0..127
    const float* hprev = g_h[t & 1];
    float*       hnext = g_h[(t + 1) & 1];

    const int kg  = tid >> 7;          // k-group 0/1
    const int lid = tid & 127;
    const int c2  = lid & 15;          // column pair -> c = 2c2, 2c2+1
    const int b4  = lid >> 4;          // 0..7 -> b = b4 + {0,8,16,24}

    u64 acc[4][2];
    #pragma unroll
    for (int i = 0; i < 4; i++) { acc[i][0] = 0ULL; acc[i][1] = 0ULL; }

    for (int kc = 0; kc < KIN; kc += CHUNK) {
        // stage h: 32 x 128 floats (1024 float4, 4 per thread)
        #pragma unroll
        for (int it = 0; it < 4; it++) {
            int e = tid + 256*it;
            int row = e >> 5, col4 = e & 31;
            float4 v = *(const float4*)(hprev + row*KIN + kc + col4*4);
            *(float4*)&hs[row][col4*4] = v;
        }
        // stage W: 32 rows x 64 k-pairs (8 float2 per thread), rotated by c>>1
        #pragma unroll
        for (int it = 0; it < 8; it++) {
            int e = tid + 256*it;
            int c = e >> 6, kp = e & 63;
            int n = (c >> 3)*H_ + jb*JT + (c & 7);
            float2 v = *(const float2*)(Whh + (size_t)n*KIN + kc + kp*2);
            ws[c][(kp + (c >> 1)) & 63] = pack2(v.x, v.y);
        }
        __syncthreads();

        const int kp0 = kg * 32;
        #pragma unroll 8
        for (int kk = 0; kk < 32; kk++) {
            int kp  = kp0 + kk;
            int widx = (kp + c2) & 63;           // matches store rotation
            u64 h0v = *(const u64*)&hs[b4     ][2*kp];
            u64 h1v = *(const u64*)&hs[b4 + 8 ][2*kp];
            u64 h2v = *(const u64*)&hs[b4 + 16][2*kp];
            u64 h3v = *(const u64*)&hs[b4 + 24][2*kp];
            u64 w0  = ws[2*c2    ][widx];
            u64 w1  = ws[2*c2 + 1][widx];
            fma2(acc[0][0], h0v, w0); fma2(acc[0][1], h0v, w1);
            fma2(acc[1][0], h1v, w0); fma2(acc[1][1], h1v, w1);
            fma2(acc[2][0], h2v, w0); fma2(acc[2][1], h2v, w1);
            fma2(acc[3][0], h3v, w0); fma2(acc[3][1], h3v, w1);
        }
        __syncthreads();
    }

    // horizontal add of k-pair partials
    float p[4][2];
    #pragma unroll
    for (int bi = 0; bi < 4; bi++) {
        #pragma unroll
        for (int q = 0; q < 2; q++) {
            float2 v = unpack2(acc[bi][q]);
            p[bi][q] = v.x + v.y;
        }
    }
    const int bs0 = b4;  // b = bs0 + 8*bi

    if (kg == 0) {
        #pragma unroll
        for (int bi = 0; bi < 4; bi++) {
            int b = bs0 + 8*bi;
            #pragma unroll
            for (int q = 0; q < 2; q++) {
                int c = 2*c2 + q;
                int n = (c >> 3)*H_ + jb*JT + (c & 7);
                sp[c][b] = p[bi][q]
                         + g_xproj[((size_t)b*T_ + t)*G_ + n]
                         + bhh[n];
            }
        }
    }
    __syncthreads();
    if (kg == 1) {
        #pragma unroll
        for (int bi = 0; bi < 4; bi++) {
            int b = bs0 + 8*bi;
            #pragma unroll
            for (int q = 0; q < 2; q++) {
                int c = 2*c2 + q;
                sp[c][b] += p[bi][q];
            }
        }
    }
    __syncthreads();

    // cell update: 256 threads = 32 b x 8 jj
    {
        int b  = tid & 31;
        int jj = tid >> 5;
        float pi = sp[0*JT + jj][b];
        float pf = sp[1*JT + jj][b];
        float po = sp[2*JT + jj][b];
        float pg = sp[3*JT + jj][b];
        float ig = 1.f / (1.f + expf(-pi));
        float fg = 1.f / (1.f + expf(-pf));
        float og = 1.f / (1.f + expf(-po));
        float gg = tanhf(pg);
        int j = jb*JT + jj;
        float cold = g_c[(size_t)j*B_ + b];        // [j][b]-major (coalesced)
        float cn = cold*fg + ig*gg;
        g_c[(size_t)j*B_ + b] = cn;
        float hn = og * tanhf(cn);
        hnext[(size_t)b*H_ + j] = hn;
        out[((size_t)b*T_ + t)*H_ + j] = hn;
        if (t == T_-1) {
            out[(size_t)B_*T_*H_ + (size_t)b*H_ + j]            = hn;  // h_f
            out[(size_t)B_*T_*H_ + (size_t)B_*H_ + (size_t)b*H_ + j] = cn; // c_f
        }
    }
}

__global__ void init_state(const float* __restrict__ h0,
                           const float* __restrict__ c0)
{
    int i = blockIdx.x*blockDim.x + threadIdx.x;   // exactly B_*H_ threads
    int b = i / H_, j = i % H_;
    g_h[0][i] = h0[i];
    g_c[(size_t)j*B_ + b] = c0[i];
}

extern "C" void kernel_launch(void* const* d_in, const int* in_sizes, int n_in,
                              void* d_out, int out_size)
{
    (void)in_sizes; (void)n_in; (void)out_size;
    const float* inputs = (const float*)d_in[0];
    const float* h0     = (const float*)d_in[1];
    const float* c0     = (const float*)d_in[2];
    const float* Wih    = (const float*)d_in[3];
    const float* bih    = (const float*)d_in[4];
    const float* Whh    = (const float*)d_in[5];
    const float* bhh    = (const float*)d_in[6];
    float* out = (float*)d_out;

    init_state<<<(B_*H_)/256, 256>>>(h0, c0);
    xproj_kernel<<<dim3(G_/P1_BN, M_/P1_BM), 256>>>(inputs, Wih, bih);
    for (int t = 0; t < T_; t++)
        lstm_step_kernel<<<H_/JT, 256>>>(Whh, bhh, out, t);
}

// round 2
// speedup vs baseline: 1.1847x; 1.1847x over previous
#include <cuda_runtime.h>
#include <cstdint>
#include <cstddef>

#define B_   32
#define T_   512
#define KIN  1024
#define H_   1024
#define G_   4096          // 4*H
#define M_   (B_*T_)       // 16384
#define JT   8             // j-units per block
#define NBLK 128           // persistent grid

// Scratch (device globals: allocation-free per harness rules)
__device__ float g_xproj[(size_t)M_ * G_];   // 256 MB: x@W_ih^T + b_ih
__device__ float g_h[2][B_*H_];              // double-buffered hidden state
__device__ float g_c[B_*H_];                 // init cell state, [jb][b][jj]

// grid barrier state
__device__ unsigned g_cnt = 0;
__device__ volatile unsigned g_gen = 0;

typedef unsigned long long u64;

// sm_103a packed fp32 FMA (2 MACs/issue; ptxas won't auto-fuse — PTX only)
__device__ __forceinline__ void fma2(u64 &d, u64 a, u64 b){
    asm("fma.rn.f32x2 %0, %1, %2, %0;" : "+l"(d) : "l"(a), "l"(b));
}
__device__ __forceinline__ u64 pack2(float lo, float hi){
    u64 r; asm("mov.b64 %0, {%1,%2};" : "=l"(r) : "f"(lo), "f"(hi)); return r;
}
__device__ __forceinline__ float2 unpack2(u64 v){
    float2 f; asm("mov.b64 {%0,%1}, %2;" : "=f"(f.x), "=f"(f.y) : "l"(v)); return f;
}

// ------------------------------------------------------------------
// Phase 1: g_xproj[m][n] = sum_k inputs[m][k]*W_ih[n][k] + b_ih[n]
// (unchanged from round 1 — ~2.5 ms, near its f32x2 floor)
// ------------------------------------------------------------------
#define P1_BM 64
#define P1_BN 64
#define P1_BK 16

__global__ void __launch_bounds__(256, 2) xproj_kernel(
    const float* __restrict__ A,
    const float* __restrict__ W,
    const float* __restrict__ bias)
{
    __shared__ __align__(16) u64   As2[P1_BK][P1_BM + 1];
    __shared__ __align__(16) float Bst[P1_BK][P1_BN + 2];

    const int tid = threadIdx.x;
    const int m0 = blockIdx.y * P1_BM;
    const int n0 = blockIdx.x * P1_BN;
    const int tx = tid & 15;
    const int ty = tid >> 4;
    const int lrow = tid >> 2;
    const int lk   = (tid & 3) * 4;

    u64 acc[4][2];
    #pragma unroll
    for (int i = 0; i < 4; i++) { acc[i][0] = 0ULL; acc[i][1] = 0ULL; }

    const float* Arow = A + (size_t)(m0 + lrow) * KIN + lk;
    const float* Wrow = W + (size_t)(n0 + lrow) * KIN + lk;

    for (int kc = 0; kc < KIN; kc += P1_BK) {
        float4 av = *(const float4*)(Arow + kc);
        float4 wv = *(const float4*)(Wrow + kc);
        As2[lk+0][lrow] = pack2(av.x, av.x);
        As2[lk+1][lrow] = pack2(av.y, av.y);
        As2[lk+2][lrow] = pack2(av.z, av.z);
        As2[lk+3][lrow] = pack2(av.w, av.w);
        Bst[lk+0][lrow] = wv.x;
        Bst[lk+1][lrow] = wv.y;
        Bst[lk+2][lrow] = wv.z;
        Bst[lk+3][lrow] = wv.w;
        __syncthreads();

        #pragma unroll
        for (int k = 0; k < P1_BK; k++) {
            u64 a0 = As2[k][ty*4+0];
            u64 a1 = As2[k][ty*4+1];
            u64 a2 = As2[k][ty*4+2];
            u64 a3 = As2[k][ty*4+3];
            u64 b0 = *(const u64*)&Bst[k][tx*4];
            u64 b1 = *(const u64*)&Bst[k][tx*4+2];
            fma2(acc[0][0], a0, b0); fma2(acc[0][1], a0, b1);
            fma2(acc[1][0], a1, b0); fma2(acc[1][1], a1, b1);
            fma2(acc[2][0], a2, b0); fma2(acc[2][1], a2, b1);
            fma2(acc[3][0], a3, b0); fma2(acc[3][1], a3, b1);
        }
        __syncthreads();
    }

    #pragma unroll
    for (int i = 0; i < 4; i++) {
        int m = m0 + ty*4 + i;
        float* crow = g_xproj + (size_t)m * G_ + n0 + tx*4;
        #pragma unroll
        for (int j = 0; j < 2; j++) {
            float2 v = unpack2(acc[i][j]);
            int n = n0 + tx*4 + 2*j;
            crow[2*j]   = v.x + bias[n];
            crow[2*j+1] = v.y + bias[n+1];
        }
    }
}

// ------------------------------------------------------------------
// Phase 2: persistent LSTM scan. 128 blocks x 256 threads, all resident.
// Block jb owns 32 preact columns (4 gates x 8 j-units).
// Lane = column; warp w owns k-range [w*128, w*128+128).
// W_hh slice lives in 64 u64 registers per lane for ALL 512 steps.
// Inner loop: lane-uniform broadcast LDS.128 of h + fma2 -> fma-bound.
// ------------------------------------------------------------------

__device__ __forceinline__ void grid_barrier(unsigned nb)
{
    __syncthreads();
    if (threadIdx.x == 0) {
        __threadfence();
        unsigned gen = g_gen;
        if (atomicAdd(&g_cnt, 1u) == nb - 1u) {
            g_cnt = 0;
            __threadfence();
            g_gen = gen + 1u;
        } else {
            while (g_gen == gen) { }
        }
        __threadfence();
    }
    __syncthreads();
}

// dynamic smem layout (floats):
//   hs  : [8][32][128]  = 32768   h slices per warp
//   pbuf: [8][32][33]   =  8448   per-warp partials
//   sp  : [32][33]      =  1056   reduced preacts
#define HS_FLOATS   (8*32*128)
#define PB_FLOATS   (8*32*33)
#define SP_FLOATS   (32*33)
#define SMEM_BYTES  ((HS_FLOATS + PB_FLOATS + SP_FLOATS)*4)

extern __shared__ float smemf[];

__global__ void __launch_bounds__(256, 1) lstm_persistent(
    const float* __restrict__ Whh,
    const float* __restrict__ bhh,
    float* __restrict__ out)
{
    float* hs   = smemf;
    float* pbuf = smemf + HS_FLOATS;
    float* sp   = pbuf + PB_FLOATS;

    const int tid = threadIdx.x;
    const int jb  = blockIdx.x;
    const int w   = tid >> 5;          // warp 0..7
    const int c   = tid & 31;          // column 0..31 (gate*8 + jj)
    const int n_c = (c >> 3)*H_ + jb*JT + (c & 7);   // W_hh row

    // --- load W slice into registers (once, for all 512 steps) ---
    u64 wreg[64];
    {
        const float4* wp = (const float4*)(Whh + (size_t)n_c*KIN + w*128);
        #pragma unroll
        for (int m = 0; m < 32; m++) {
            float4 v = wp[m];
            wreg[2*m]   = pack2(v.x, v.y);
            wreg[2*m+1] = pack2(v.z, v.w);
        }
    }

    // --- cell-update thread mapping: (b, jj), coalesced h/out writes ---
    const int ub = tid >> 3;           // batch 0..31
    const int uj = tid & 7;            // j-unit 0..7
    const int jg = jb*JT + uj;         // global j

    float bh[4];
    #pragma unroll
    for (int g = 0; g < 4; g++) bh[g] = bhh[g*H_ + jg];

    float cstate = g_c[jb*256 + ub*8 + uj];   // cell state in a register

    const size_t OFF_H = (size_t)B_*T_*H_;
    const size_t OFF_C = OFF_H + (size_t)B_*H_;

    for (int t = 0; t < T_; t++) {
        const float* hprev = g_h[t & 1];
        float*       hnext = g_h[(t + 1) & 1];

        // prefetch xproj slice early (lands during mainloop)
        float xp[4];
        #pragma unroll
        for (int g = 0; g < 4; g++)
            xp[g] = g_xproj[((size_t)ub*T_ + t)*G_ + g*H_ + jg];

        // stage this warp's h k-slice: hs[w][b][0..127]
        {
            const float4* hsrc = (const float4*)hprev;
            float4* dst = (float4*)(hs + w*32*128);
            #pragma unroll 8
            for (int b = 0; b < 32; b++)
                dst[b*32 + c] = hsrc[b*256 + w*32 + c];
        }
        __syncwarp();

        // mainloop: per b, 32 broadcast LDS.128 + 64 fma2 (2 acc chains)
        {
            float* prow = pbuf + (w*32 + c)*33;
            #pragma unroll 2
            for (int b = 0; b < 32; b++) {
                const ulonglong2* hb =
                    (const ulonglong2*)(hs + (w*32 + b)*128);
                u64 a0 = 0ULL, a1 = 0ULL;
                #pragma unroll
                for (int m = 0; m < 32; m++) {
                    ulonglong2 hv = hb[m];
                    fma2(a0, wreg[2*m],   hv.x);
                    fma2(a1, wreg[2*m+1], hv.y);
                }
                float2 f0 = unpack2(a0), f1 = unpack2(a1);
                prow[b] = (f0.x + f0.y) + (f1.x + f1.y);
            }
        }
        __syncthreads();

        // reduce 8 warp-partials: thread handles (cc, b0..b0+3)
        {
            int cc = tid >> 3, b0 = (tid & 7) * 4;
            float s0 = 0.f, s1 = 0.f, s2 = 0.f, s3 = 0.f;
            #pragma unroll
            for (int ww = 0; ww < 8; ww++) {
                const float* pr = pbuf + (ww*32 + cc)*33 + b0;
                s0 += pr[0]; s1 += pr[1]; s2 += pr[2]; s3 += pr[3];
            }
            float* sr = sp + cc*33 + b0;
            sr[0] = s0; sr[1] = s1; sr[2] = s2; sr[3] = s3;
        }
        __syncthreads();

        // gates + cell update: thread (ub, uj)
        {
            float pre[4];
            #pragma unroll
            for (int g = 0; g < 4; g++)
                pre[g] = sp[(g*8 + uj)*33 + ub] + xp[g] + bh[g];

            float ig = 1.f / (1.f + __expf(-pre[0]));
            float fg = 1.f / (1.f + __expf(-pre[1]));
            float og = 1.f / (1.f + __expf(-pre[2]));
            float gg = tanhf(pre[3]);
            cstate = cstate * fg + ig * gg;
            float hn = og * tanhf(cstate);

            hnext[ub*H_ + jg] = hn;
            out[((size_t)ub*T_ + t)*H_ + jg] = hn;
            if (t == T_ - 1) {
                out[OFF_H + (size_t)ub*H_ + jg] = hn;
                out[OFF_C + (size_t)ub*H_ + jg] = cstate;
            }
        }

        if (t + 1 < T_) grid_barrier(NBLK);
    }
}

__global__ void init_state(const float* __restrict__ h0,
                           const float* __restrict__ c0)
{
    int i = blockIdx.x*blockDim.x + threadIdx.x;   // exactly B_*H_ threads
    int b = i / H_, j = i % H_;
    g_h[0][i] = h0[i];
    g_c[(j >> 3)*256 + b*8 + (j & 7)] = c0[i];
}

extern "C" void kernel_launch(void* const* d_in, const int* in_sizes, int n_in,
                              void* d_out, int out_size)
{
    (void)in_sizes; (void)n_in; (void)out_size;
    const float* inputs = (const float*)d_in[0];
    const float* h0     = (const float*)d_in[1];
    const float* c0     = (const float*)d_in[2];
    const float* Wih    = (const float*)d_in[3];
    const float* bih    = (const float*)d_in[4];
    const float* Whh    = (const float*)d_in[5];
    const float* bhh    = (const float*)d_in[6];
    float* out = (float*)d_out;

    cudaFuncSetAttribute(lstm_persistent,
                         cudaFuncAttributeMaxDynamicSharedMemorySize,
                         SMEM_BYTES);

    init_state<<<(B_*H_)/256, 256>>>(h0, c0);
    xproj_kernel<<<dim3(G_/P1_BN, M_/P1_BM), 256>>>(inputs, Wih, bih);
    lstm_persistent<<<NBLK, 256, SMEM_BYTES>>>(Whh, bhh, out);
}

// round 3
// speedup vs baseline: 1.1970x; 1.0104x over previous
#include <cuda_runtime.h>
#include <cstdint>
#include <cstddef>

#define B_   32
#define T_   512
#define KIN  1024
#define H_   1024
#define G_   4096          // 4*H
#define M_   (B_*T_)       // 16384
#define JT   8             // j-units per block
#define NBLK 128           // persistent grid
#define NTHR 512           // threads per persistent block (16 warps)

// Scratch (device globals: allocation-free per harness rules)
__device__ float g_xproj[(size_t)M_ * G_];   // 256 MB: x@W_ih^T + b_ih
__device__ float g_h[2][B_*H_];              // double-buffered hidden state
__device__ float g_c[B_*H_];                 // init cell state, [jb][b][jj]

// grid barrier state
__device__ unsigned g_cnt = 0;
__device__ volatile unsigned g_gen = 0;

typedef unsigned long long u64;

// sm_103a packed fp32 FMA (2 MACs/issue; ptxas won't auto-fuse — PTX only)
__device__ __forceinline__ void fma2(u64 &d, u64 a, u64 b){
    asm("fma.rn.f32x2 %0, %1, %2, %0;" : "+l"(d) : "l"(a), "l"(b));
}
__device__ __forceinline__ u64 pack2(float lo, float hi){
    u64 r; asm("mov.b64 %0, {%1,%2};" : "=l"(r) : "f"(lo), "f"(hi)); return r;
}
__device__ __forceinline__ float2 unpack2(u64 v){
    float2 f; asm("mov.b64 {%0,%1}, %2;" : "=f"(f.x), "=f"(f.y) : "l"(v)); return f;
}

// ------------------------------------------------------------------
// Phase 1: g_xproj[m][n] = sum_k inputs[m][k]*W_ih[n][k] + b_ih[n]
// (unchanged — ~2.5 ms; tensor-core rewrite is a later round)
// ------------------------------------------------------------------
#define P1_BM 64
#define P1_BN 64
#define P1_BK 16

__global__ void __launch_bounds__(256, 2) xproj_kernel(
    const float* __restrict__ A,
    const float* __restrict__ W,
    const float* __restrict__ bias)
{
    __shared__ __align__(16) u64   As2[P1_BK][P1_BM + 1];
    __shared__ __align__(16) float Bst[P1_BK][P1_BN + 2];

    const int tid = threadIdx.x;
    const int m0 = blockIdx.y * P1_BM;
    const int n0 = blockIdx.x * P1_BN;
    const int tx = tid & 15;
    const int ty = tid >> 4;
    const int lrow = tid >> 2;
    const int lk   = (tid & 3) * 4;

    u64 acc[4][2];
    #pragma unroll
    for (int i = 0; i < 4; i++) { acc[i][0] = 0ULL; acc[i][1] = 0ULL; }

    const float* Arow = A + (size_t)(m0 + lrow) * KIN + lk;
    const float* Wrow = W + (size_t)(n0 + lrow) * KIN + lk;

    for (int kc = 0; kc < KIN; kc += P1_BK) {
        float4 av = *(const float4*)(Arow + kc);
        float4 wv = *(const float4*)(Wrow + kc);
        As2[lk+0][lrow] = pack2(av.x, av.x);
        As2[lk+1][lrow] = pack2(av.y, av.y);
        As2[lk+2][lrow] = pack2(av.z, av.z);
        As2[lk+3][lrow] = pack2(av.w, av.w);
        Bst[lk+0][lrow] = wv.x;
        Bst[lk+1][lrow] = wv.y;
        Bst[lk+2][lrow] = wv.z;
        Bst[lk+3][lrow] = wv.w;
        __syncthreads();

        #pragma unroll
        for (int k = 0; k < P1_BK; k++) {
            u64 a0 = As2[k][ty*4+0];
            u64 a1 = As2[k][ty*4+1];
            u64 a2 = As2[k][ty*4+2];
            u64 a3 = As2[k][ty*4+3];
            u64 b0 = *(const u64*)&Bst[k][tx*4];
            u64 b1 = *(const u64*)&Bst[k][tx*4+2];
            fma2(acc[0][0], a0, b0); fma2(acc[0][1], a0, b1);
            fma2(acc[1][0], a1, b0); fma2(acc[1][1], a1, b1);
            fma2(acc[2][0], a2, b0); fma2(acc[2][1], a2, b1);
            fma2(acc[3][0], a3, b0); fma2(acc[3][1], a3, b1);
        }
        __syncthreads();
    }

    #pragma unroll
    for (int i = 0; i < 4; i++) {
        int m = m0 + ty*4 + i;
        float* crow = g_xproj + (size_t)m * G_ + n0 + tx*4;
        #pragma unroll
        for (int j = 0; j < 2; j++) {
            float2 v = unpack2(acc[i][j]);
            int n = n0 + tx*4 + 2*j;
            crow[2*j]   = v.x + bias[n];
            crow[2*j+1] = v.y + bias[n+1];
        }
    }
}

// ------------------------------------------------------------------
// Phase 2: persistent LSTM scan. 128 blocks x 512 threads (16 warps).
// Block jb owns 32 preact columns (4 gates x 8 j-units).
// Lane = column; warp w owns k-slice [w*64, w*64+64).
// W_hh slice: 32 u64 regs/lane (64 regs) -> no spill risk at 128-reg cap.
// Inner loop: broadcast LDS.128 of h + fma2 -> fma-pipe bound.
// ------------------------------------------------------------------

__device__ __forceinline__ void grid_barrier(unsigned nb)
{
    __syncthreads();
    if (threadIdx.x == 0) {
        __threadfence();
        unsigned gen = g_gen;
        if (atomicAdd(&g_cnt, 1u) == nb - 1u) {
            g_cnt = 0;
            __threadfence();
            g_gen = gen + 1u;
        } else {
            while (g_gen == gen) { }
        }
        __threadfence();
    }
    __syncthreads();
}

// dynamic smem layout (floats):
//   hs  : [32][HP]      h, HP-pitch rows
//   pbuf: [16][32][33]  per-warp partials
//   sp  : [32][33]      reduced preacts
#define HP          1028
#define HS_FLOATS   (32*HP)
#define PB_FLOATS   (16*32*33)
#define SP_FLOATS   (32*33)
#define SMEM_BYTES  ((HS_FLOATS + PB_FLOATS + SP_FLOATS)*4)
#define PBUF(w,c,b) pbuf[(w)*(32*33) + (c)*33 + (b)]

extern __shared__ float smemf[];

__global__ void __launch_bounds__(NTHR, 1) lstm_persistent(
    const float* __restrict__ Whh,
    const float* __restrict__ bhh,
    float* __restrict__ out)
{
    float* hs   = smemf;
    float* pbuf = smemf + HS_FLOATS;
    float* sp   = pbuf + PB_FLOATS;

    const int tid = threadIdx.x;
    const int jb  = blockIdx.x;
    const int w   = tid >> 5;          // warp 0..15
    const int c   = tid & 31;          // column 0..31 (gate*8 + jj)
    const int n_c = (c >> 3)*H_ + jb*JT + (c & 7);   // W_hh row

    // --- load W slice into registers (once, for all 512 steps) ---
    u64 wreg[32];
    {
        const float4* wp = (const float4*)(Whh + (size_t)n_c*KIN + w*64);
        #pragma unroll
        for (int m = 0; m < 16; m++) {
            float4 v = wp[m];
            wreg[2*m]   = pack2(v.x, v.y);
            wreg[2*m+1] = pack2(v.z, v.w);
        }
    }

    // --- cell-update mapping (threads 0..255): (b, jj) ---
    const bool upd = (tid < 256);
    const int ub = (tid >> 3) & 31;    // batch 0..31
    const int uj = tid & 7;            // j-unit 0..7
    const int jg = jb*JT + uj;         // global j

    float bh0=0.f, bh1=0.f, bh2=0.f, bh3=0.f, cstate=0.f;
    if (upd) {
        bh0 = bhh[0*H_ + jg];
        bh1 = bhh[1*H_ + jg];
        bh2 = bhh[2*H_ + jg];
        bh3 = bhh[3*H_ + jg];
        cstate = g_c[jb*256 + ub*8 + uj];
    }

    const size_t OFF_H = (size_t)B_*T_*H_;
    const size_t OFF_C = OFF_H + (size_t)B_*H_;

    for (int t = 0; t < T_; t++) {
        const float* hprev = g_h[t & 1];
        float*       hnext = g_h[(t + 1) & 1];

        // prefetch xproj slice (lands during mainloop)
        float xp0=0.f, xp1=0.f, xp2=0.f, xp3=0.f;
        if (upd) {
            const float* xrow = g_xproj + ((size_t)ub*T_ + t)*G_ + jg;
            xp0 = xrow[0*H_]; xp1 = xrow[1*H_];
            xp2 = xrow[2*H_]; xp3 = xrow[3*H_];
        }

        // stage h: 32 x 1024 floats = 8192 float4, block-wide coalesced
        {
            const float4* hsrc = (const float4*)hprev;
            #pragma unroll
            for (int it = 0; it < 16; it++) {
                int e = tid + NTHR*it;          // 0..8191
                int row = e >> 8, col4 = e & 255;
                *(float4*)(hs + row*HP + col4*4) = hsrc[row*256 + col4];
            }
        }
        __syncthreads();

        // mainloop: per b, 16 broadcast LDS.128 + 32 fma2 (2 chains)
        {
            float* prow = &PBUF(w, c, 0);
            #pragma unroll 2
            for (int b = 0; b < 32; b++) {
                const ulonglong2* hb = (const ulonglong2*)(hs + b*HP + w*64);
                u64 a0 = 0ULL, a1 = 0ULL;
                #pragma unroll
                for (int m = 0; m < 16; m++) {
                    ulonglong2 hv = hb[m];
                    fma2(a0, wreg[2*m],   hv.x);
                    fma2(a1, wreg[2*m+1], hv.y);
                }
                float2 f0 = unpack2(a0), f1 = unpack2(a1);
                prow[b] = (f0.x + f0.y) + (f1.x + f1.y);
            }
        }
        __syncthreads();

        // reduce 16 warp-partials: thread -> (cc, 2 consecutive b)
        {
            int cc = tid >> 4, bb = (tid & 15) * 2;
            float s0 = 0.f, s1 = 0.f;
            #pragma unroll
            for (int ww = 0; ww < 16; ww++) {
                s0 += PBUF(ww, cc, bb);
                s1 += PBUF(ww, cc, bb+1);
            }
            sp[cc*33 + bb]   = s0;
            sp[cc*33 + bb+1] = s1;
        }
        __syncthreads();

        // gates + cell update: threads 0..255, thread (ub, uj)
        if (upd) {
            float p0 = sp[(0*8 + uj)*33 + ub] + xp0 + bh0;
            float p1 = sp[(1*8 + uj)*33 + ub] + xp1 + bh1;
            float p2 = sp[(2*8 + uj)*33 + ub] + xp2 + bh2;
            float p3 = sp[(3*8 + uj)*33 + ub] + xp3 + bh3;

            float ig = 1.f / (1.f + __expf(-p0));
            float fg = 1.f / (1.f + __expf(-p1));
            float og = 1.f / (1.f + __expf(-p2));
            float gg = tanhf(p3);
            cstate = cstate * fg + ig * gg;
            float hn = og * tanhf(cstate);

            hnext[ub*H_ + jg] = hn;
            out[((size_t)ub*T_ + t)*H_ + jg] = hn;
            if (t == T_ - 1) {
                out[OFF_H + (size_t)ub*H_ + jg] = hn;
                out[OFF_C + (size_t)ub*H_ + jg] = cstate;
            }
        }

        if (t + 1 < T_) grid_barrier(NBLK);
    }
}

__global__ void init_state(const float* __restrict__ h0,
                           const float* __restrict__ c0)
{
    int i = blockIdx.x*blockDim.x + threadIdx.x;   // exactly B_*H_ threads
    int b = i / H_, j = i % H_;
    g_h[0][i] = h0[i];
    g_c[(j >> 3)*256 + b*8 + (j & 7)] = c0[i];
}

extern "C" void kernel_launch(void* const* d_in, const int* in_sizes, int n_in,
                              void* d_out, int out_size)
{
    (void)in_sizes; (void)n_in; (void)out_size;
    const float* inputs = (const float*)d_in[0];
    const float* h0     = (const float*)d_in[1];
    const float* c0     = (const float*)d_in[2];
    const float* Wih    = (const float*)d_in[3];
    const float* bih    = (const float*)d_in[4];
    const float* Whh    = (const float*)d_in[5];
    const float* bhh    = (const float*)d_in[6];
    float* out = (float*)d_out;

    cudaFuncSetAttribute(lstm_persistent,
                         cudaFuncAttributeMaxDynamicSharedMemorySize,
                         SMEM_BYTES);

    init_state<<<(B_*H_)/256, 256>>>(h0, c0);
    xproj_kernel<<<dim3(G_/P1_BN, M_/P1_BM), 256>>>(inputs, Wih, bih);
    lstm_persistent<<<NBLK, NTHR, SMEM_BYTES>>>(Whh, bhh, out);
}